// round 8
// baseline (speedup 1.0000x reference)
#include <cuda_runtime.h>

#define T_STEPS 512
#define B_SZ    256
#define H_SZ    256
#define LDIM    128
#define NCTA    128   // 64 unit-slices x 2 batch-halves
#define NT      256   // threads: 4 units x 64 batch-pairs

typedef unsigned long long u64;

// static device scratch (no allocations allowed)
__device__ float g_h0[2][H_SZ * B_SZ];              // [parity][unit][batch]
__device__ float g_h1[2][H_SZ * B_SZ];
__device__ float g_part[64 * B_SZ * T_STEPS];       // [us][b][t]
__device__ u64   g_ctr = 0;

// ---------------- helpers ----------------
__device__ __forceinline__ void fma2(u64 &d, u64 a, u64 b) {
    asm("fma.rn.f32x2 %0, %1, %2, %0;" : "+l"(d) : "l"(a), "l"(b));
}
__device__ __forceinline__ u64 pack2(float lo, float hi) {
    u64 r; asm("mov.b64 %0, {%1, %2};" : "=l"(r) : "f"(lo), "f"(hi)); return r;
}
__device__ __forceinline__ void unpack2(u64 v, float &lo, float &hi) {
    asm("mov.b64 {%0, %1}, %2;" : "=f"(lo), "=f"(hi) : "l"(v));
}
__device__ __forceinline__ float ex2f(float x) {
    float r; asm("ex2.approx.f32 %0, %1;" : "=f"(r) : "f"(x)); return r;
}
__device__ __forceinline__ float rcpf(float x) {
    float r; asm("rcp.approx.f32 %0, %1;" : "=f"(r) : "f"(x)); return r;
}
__device__ __forceinline__ float sigf(float x) {
    return rcpf(1.0f + ex2f(-1.4426950408889634f * x));
}
__device__ __forceinline__ float tanhf_(float x) {
    float e = ex2f(2.8853900817779268f * x);   // e^{2x}
    return 1.0f - 2.0f * rcpf(e + 1.0f);
}

// re-entrant grid barrier: monotonic counter, graph-replay safe
__device__ __forceinline__ void grid_sync() {
    __syncthreads();
    if (threadIdx.x == 0) {
        u64 old;
        asm volatile("atom.release.gpu.add.u64 %0, [%1], %2;"
                     : "=l"(old) : "l"(&g_ctr), "l"(1ULL) : "memory");
        u64 target = (old / NCTA + 1ULL) * (u64)NCTA;
        u64 v;
        do {
            asm volatile("ld.acquire.gpu.u64 %0, [%1];"
                         : "=l"(v) : "l"(&g_ctr) : "memory");
        } while (v < target);
    }
    __syncthreads();
}

// accumulate NK k-steps: acc[4 gates] over this thread's batch pair.
// hsrc: [k][batch] base; wsm: smem, per-k stride 32 floats (4 gates dup'd, this u)
template <int NK>
__device__ __forceinline__ void accum_span(u64 acc[4],
                                           const float* __restrict__ hsrc,
                                           const float* __restrict__ wsm,
                                           int bbase) {
    constexpr int G  = 16;
    constexpr int NG = NK / G;
    u64 hbuf[G];
#pragma unroll
    for (int i = 0; i < G; ++i)
        hbuf[i] = *reinterpret_cast<const u64*>(hsrc + i * B_SZ + bbase);
#pragma unroll 2
    for (int g = 0; g < NG; ++g) {
        u64 hnext[G];
        if (g + 1 < NG) {
#pragma unroll
            for (int i = 0; i < G; ++i)
                hnext[i] = *reinterpret_cast<const u64*>(
                    hsrc + ((g + 1) * G + i) * B_SZ + bbase);
        }
#pragma unroll
        for (int i = 0; i < G; ++i) {
            const ulonglong2* wp =
                reinterpret_cast<const ulonglong2*>(wsm + (g * G + i) * 32);
            ulonglong2 wab = wp[0];   // {wi,wi},{wf,wf}
            ulonglong2 wcd = wp[1];   // {wg,wg},{wo,wo}
            u64 hv = hbuf[i];
            fma2(acc[0], hv, wab.x);
            fma2(acc[1], hv, wab.y);
            fma2(acc[2], hv, wcd.x);
            fma2(acc[3], hv, wcd.y);
        }
        if (g + 1 < NG) {
#pragma unroll
            for (int i = 0; i < G; ++i) hbuf[i] = hnext[i];
        }
    }
}

// ---------------- prologue: h_init = latent @ W_lh^T + b_lh ----------------
__global__ void init_kernel(const float* __restrict__ latent,
                            const float* __restrict__ W_lh,
                            const float* __restrict__ b_lh) {
    __shared__ float lat[LDIM];
    int b = blockIdx.x, j = threadIdx.x;
    if (j < LDIM) lat[j] = latent[b * LDIM + j];
    __syncthreads();
    float acc = b_lh[j];
    const float* wr = W_lh + j * LDIM;
#pragma unroll 8
    for (int l = 0; l < LDIM; ++l) acc = fmaf(lat[l], wr[l], acc);
    g_h0[0][j * B_SZ + b] = acc;
    g_h1[0][j * B_SZ + b] = acc;
}

// ---------------- persistent rollout ----------------
// CTA r: us = r>>1 owns units [us*4, us*4+4), bh = r&1 owns batches [bh*128,+128)
// thread: u = tid>>6 (0..3), bp = tid&63 -> batches bbase=bh*128+bp*2 (+0,+1)
__global__ void __launch_bounds__(NT, 1) lstm_kernel(
    const float* __restrict__ W_hh0,
    const float* __restrict__ b_ih0, const float* __restrict__ b_hh0,
    const float* __restrict__ W_ih1, const float* __restrict__ W_hh1,
    const float* __restrict__ b_ih1, const float* __restrict__ b_hh1,
    const float* __restrict__ W_ho)
{
    extern __shared__ float smem[];
    float* w0  = smem;                 // [k=256][u=4][gate=4][dup=2] = 8192 f
    float* w1  = smem + 8192;          // [k=512][u][gate][dup]      = 16384 f
    float* red = smem + 24576;         // [u=4][bp=64][2]            = 512 f

    const int tid   = threadIdx.x;
    const int us    = blockIdx.x >> 1;
    const int bh    = blockIdx.x & 1;
    const int u     = tid >> 6;
    const int bp    = tid & 63;
    const int bbase = bh * 128 + bp * 2;
    const int gu    = us * 4 + u;

    // stage duplicated weight slices
    for (int idx = tid; idx < 256 * 16; idx += NT) {
        int k = idx >> 4, rem = idx & 15, uu = rem >> 2, gate = rem & 3;
        float w = W_hh0[(gate * H_SZ + us * 4 + uu) * H_SZ + k];
        int o = k * 32 + uu * 8 + gate * 2;
        w0[o] = w; w0[o + 1] = w;
    }
    for (int idx = tid; idx < 512 * 16; idx += NT) {
        int k = idx >> 4, rem = idx & 15, uu = rem >> 2, gate = rem & 3;
        int row = gate * H_SZ + us * 4 + uu;
        float w = (k < 256) ? W_ih1[row * H_SZ + k]
                            : W_hh1[row * H_SZ + (k - 256)];
        int o = k * 32 + uu * 8 + gate * 2;
        w1[o] = w; w1[o + 1] = w;
    }

    float bias0[4], bias1[4];
#pragma unroll
    for (int gate = 0; gate < 4; ++gate) {
        int row = gate * H_SZ + gu;
        bias0[gate] = b_ih0[row] + b_hh0[row];
        bias1[gate] = b_ih1[row] + b_hh1[row];
    }
    const float who = W_ho[gu];

    float c0a = 0.f, c0b = 0.f, c1a = 0.f, c1b = 0.f;
    __syncthreads();

    const float* wsm0  = w0 + u * 8;
    const float* wsm1a = w1 + u * 8;
    const float* wsm1b = w1 + 256 * 32 + u * 8;

    for (int k = 1; k <= T_STEPS + 1; ++k) {
        const float* __restrict__ h0prev = g_h0[(k - 1) & 1];

        // ---- layer 0: h0_k = cell(b0, h0_{k-1}) ----
        if (k <= T_STEPS) {
            u64 acc[4];
#pragma unroll
            for (int g = 0; g < 4; ++g) acc[g] = pack2(bias0[g], bias0[g]);
            accum_span<256>(acc, h0prev, wsm0, bbase);

            float zi0, zi1, zf0, zf1, zg0, zg1, zo0, zo1;
            unpack2(acc[0], zi0, zi1); unpack2(acc[1], zf0, zf1);
            unpack2(acc[2], zg0, zg1); unpack2(acc[3], zo0, zo1);
            float cn0 = sigf(zf0) * c0a + sigf(zi0) * tanhf_(zg0);
            float cn1 = sigf(zf1) * c0b + sigf(zi1) * tanhf_(zg1);
            c0a = cn0; c0b = cn1;
            float2 ho;
            ho.x = sigf(zo0) * tanhf_(cn0);
            ho.y = sigf(zo1) * tanhf_(cn1);
            *reinterpret_cast<float2*>(g_h0[k & 1] + gu * B_SZ + bbase) = ho;
        }

        // ---- layer 1: h1_{k-1} = cell(h0_{k-1}@W_ih1^T + b1, h1_{k-2}) ----
        if (k >= 2) {
            const float* __restrict__ h1prev = g_h1[k & 1];
            u64 acc[4];
#pragma unroll
            for (int g = 0; g < 4; ++g) acc[g] = pack2(bias1[g], bias1[g]);
            accum_span<256>(acc, h0prev, wsm1a, bbase);
            accum_span<256>(acc, h1prev, wsm1b, bbase);

            float zi0, zi1, zf0, zf1, zg0, zg1, zo0, zo1;
            unpack2(acc[0], zi0, zi1); unpack2(acc[1], zf0, zf1);
            unpack2(acc[2], zg0, zg1); unpack2(acc[3], zo0, zo1);
            float cn0 = sigf(zf0) * c1a + sigf(zi0) * tanhf_(zg0);
            float cn1 = sigf(zf1) * c1b + sigf(zi1) * tanhf_(zg1);
            c1a = cn0; c1b = cn1;
            float2 ho;
            ho.x = sigf(zo0) * tanhf_(cn0);
            ho.y = sigf(zo1) * tanhf_(cn1);
            *reinterpret_cast<float2*>(g_h1[(k - 1) & 1] + gu * B_SZ + bbase) = ho;

            // output partial: reduce over this CTA's 4 units
            red[(u * 64 + bp) * 2]     = who * ho.x;
            red[(u * 64 + bp) * 2 + 1] = who * ho.y;
            __syncthreads();
            if (u == 0) {
                float s0 = red[bp * 2]           + red[(64 + bp) * 2] +
                           red[(128 + bp) * 2]   + red[(192 + bp) * 2];
                float s1 = red[bp * 2 + 1]       + red[(64 + bp) * 2 + 1] +
                           red[(128 + bp) * 2 + 1] + red[(192 + bp) * 2 + 1];
                int t0 = k - 2;
                g_part[(us * B_SZ + bbase)     * T_STEPS + t0] = s0;
                g_part[(us * B_SZ + bbase + 1) * T_STEPS + t0] = s1;
            }
        }
        grid_sync();
    }
}

// ---------------- final: out[b][t] = b_ho + sum_us g_part[us][b][t] ----------
__global__ void reduce_kernel(const float* __restrict__ b_ho,
                              float* __restrict__ out) {
    int idx = blockIdx.x * blockDim.x + threadIdx.x;  // = b*512 + t
    float s = b_ho[0];
    const float* p = g_part + idx;
#pragma unroll 8
    for (int usx = 0; usx < 64; ++usx) s += p[usx * (B_SZ * T_STEPS)];
    out[idx] = s;
}

extern "C" void kernel_launch(void* const* d_in, const int* in_sizes, int n_in,
                              void* d_out, int out_size) {
    const float* latent = (const float*)d_in[0];
    const float* W_lh   = (const float*)d_in[1];
    const float* b_lh   = (const float*)d_in[2];
    // d_in[3] = W_ih0 (layer-0 inputs are all zero -> unused)
    const float* W_hh0  = (const float*)d_in[4];
    const float* b_ih0  = (const float*)d_in[5];
    const float* b_hh0  = (const float*)d_in[6];
    const float* W_ih1  = (const float*)d_in[7];
    const float* W_hh1  = (const float*)d_in[8];
    const float* b_ih1  = (const float*)d_in[9];
    const float* b_hh1  = (const float*)d_in[10];
    const float* W_ho   = (const float*)d_in[11];
    const float* b_ho   = (const float*)d_in[12];
    float* out = (float*)d_out;

    const int smem_bytes = (8192 + 16384 + 512) * sizeof(float);  // 100352
    cudaFuncSetAttribute(lstm_kernel,
                         cudaFuncAttributeMaxDynamicSharedMemorySize, smem_bytes);

    init_kernel<<<B_SZ, H_SZ>>>(latent, W_lh, b_lh);
    lstm_kernel<<<NCTA, NT, smem_bytes>>>(W_hh0, b_ih0, b_hh0,
                                          W_ih1, W_hh1, b_ih1, b_hh1, W_ho);
    reduce_kernel<<<(B_SZ * T_STEPS) / 256, 256>>>(b_ho, out);
    (void)in_sizes; (void)n_in; (void)out_size;
}

// round 10
// speedup vs baseline: 1.0633x; 1.0633x over previous
#include <cuda_runtime.h>

#define T_STEPS 512
#define B_SZ    256
#define H_SZ    256
#define LDIM    128
#define NCTA    128   // 64 unit-slices x 2 batch-halves
#define NT      256   // threads: 4 units x 64 batch-pairs
#define CH      64    // k-chunk rows staged per buffer

typedef unsigned long long u64;

// static device scratch (no allocations allowed)
__device__ __align__(16) float g_h0[2][H_SZ * B_SZ];   // [parity][unit][batch]
__device__ __align__(16) float g_h1[2][H_SZ * B_SZ];
__device__ float g_part[64 * B_SZ * T_STEPS];          // [us][b][t]
__device__ u64   g_ctr = 0;

// ---------------- helpers ----------------
__device__ __forceinline__ void fma2(u64 &d, u64 a, u64 b) {
    asm("fma.rn.f32x2 %0, %1, %2, %0;" : "+l"(d) : "l"(a), "l"(b));
}
__device__ __forceinline__ u64 pack2(float lo, float hi) {
    u64 r; asm("mov.b64 %0, {%1, %2};" : "=l"(r) : "f"(lo), "f"(hi)); return r;
}
__device__ __forceinline__ void unpack2(u64 v, float &lo, float &hi) {
    asm("mov.b64 {%0, %1}, %2;" : "=f"(lo), "=f"(hi) : "l"(v));
}
__device__ __forceinline__ float ex2f(float x) {
    float r; asm("ex2.approx.f32 %0, %1;" : "=f"(r) : "f"(x)); return r;
}
__device__ __forceinline__ float rcpf(float x) {
    float r; asm("rcp.approx.f32 %0, %1;" : "=f"(r) : "f"(x)); return r;
}
__device__ __forceinline__ float sigf(float x) {
    return rcpf(1.0f + ex2f(-1.4426950408889634f * x));
}
__device__ __forceinline__ float tanhf_(float x) {
    float e = ex2f(2.8853900817779268f * x);   // e^{2x}
    return 1.0f - 2.0f * rcpf(e + 1.0f);
}

// re-entrant grid barrier: monotonic counter, graph-replay safe
__device__ __forceinline__ void grid_sync() {
    __syncthreads();
    if (threadIdx.x == 0) {
        u64 old;
        asm volatile("atom.release.gpu.add.u64 %0, [%1], %2;"
                     : "=l"(old) : "l"(&g_ctr), "l"(1ULL) : "memory");
        u64 target = (old / NCTA + 1ULL) * (u64)NCTA;
        u64 v;
        do {
            asm volatile("ld.acquire.gpu.u64 %0, [%1];"
                         : "=l"(v) : "l"(&g_ctr) : "memory");
        } while (v < target);
    }
    __syncthreads();
}

// stage CH rows x 128 batch-floats from global (L2, bypass L1) into smem
__device__ __forceinline__ void stage_chunk(float* __restrict__ dst,
                                            const float* __restrict__ gsrc,
                                            int tid) {
#pragma unroll
    for (int j = 0; j < 8; ++j) {
        int idx = tid + j * NT;          // 0..2047
        int row = idx >> 5;              // 32 float4 per row
        int c4  = idx & 31;
        float4 v = __ldcg(reinterpret_cast<const float4*>(gsrc + row * B_SZ) + c4);
        reinterpret_cast<float4*>(dst)[row * 32 + c4] = v;
    }
}

// fused: accumulate acc0 (W_hh0) and acc1 (W_ih1) over one staged h0 chunk
__device__ __forceinline__ void fused_chunk(u64 acc0[4], u64 acc1[4],
                                            const float* __restrict__ sh,
                                            const float* __restrict__ w0k,
                                            const float* __restrict__ w1k,
                                            int lb) {
#pragma unroll 8
    for (int kk = 0; kk < CH; ++kk) {
        u64 hv = *reinterpret_cast<const u64*>(sh + kk * 128 + lb);
        const ulonglong2* p0 = reinterpret_cast<const ulonglong2*>(w0k + kk * 32);
        const ulonglong2* p1 = reinterpret_cast<const ulonglong2*>(w1k + kk * 32);
        ulonglong2 a0 = p0[0], b0 = p0[1];
        ulonglong2 a1 = p1[0], b1 = p1[1];
        fma2(acc0[0], hv, a0.x); fma2(acc0[1], hv, a0.y);
        fma2(acc0[2], hv, b0.x); fma2(acc0[3], hv, b0.y);
        fma2(acc1[0], hv, a1.x); fma2(acc1[1], hv, a1.y);
        fma2(acc1[2], hv, b1.x); fma2(acc1[3], hv, b1.y);
    }
}

// single: accumulate acc over one staged h1 chunk (W_hh1)
__device__ __forceinline__ void single_chunk(u64 acc[4],
                                             const float* __restrict__ sh,
                                             const float* __restrict__ wk,
                                             int lb) {
#pragma unroll 8
    for (int kk = 0; kk < CH; ++kk) {
        u64 hv = *reinterpret_cast<const u64*>(sh + kk * 128 + lb);
        const ulonglong2* p = reinterpret_cast<const ulonglong2*>(wk + kk * 32);
        ulonglong2 a = p[0], b = p[1];
        fma2(acc[0], hv, a.x); fma2(acc[1], hv, a.y);
        fma2(acc[2], hv, b.x); fma2(acc[3], hv, b.y);
    }
}

// ---------------- prologue: h_init = latent @ W_lh^T + b_lh ----------------
__global__ void init_kernel(const float* __restrict__ latent,
                            const float* __restrict__ W_lh,
                            const float* __restrict__ b_lh) {
    __shared__ float lat[LDIM];
    int b = blockIdx.x, j = threadIdx.x;
    if (j < LDIM) lat[j] = latent[b * LDIM + j];
    __syncthreads();
    float acc = b_lh[j];
    const float* wr = W_lh + j * LDIM;
#pragma unroll 8
    for (int l = 0; l < LDIM; ++l) acc = fmaf(lat[l], wr[l], acc);
    g_h0[0][j * B_SZ + b] = acc;
    g_h1[0][j * B_SZ + b] = acc;
}

// ---------------- persistent rollout ----------------
// CTA r: us = r>>1 owns units [us*4, us*4+4), bh = r&1 owns batches [bh*128,+128)
// thread: u = tid>>6 (0..3), bp = tid&63 -> batches bbase=bh*128+bp*2 (+0,+1)
__global__ void __launch_bounds__(NT, 1) lstm_kernel(
    const float* __restrict__ W_hh0,
    const float* __restrict__ b_ih0, const float* __restrict__ b_hh0,
    const float* __restrict__ W_ih1, const float* __restrict__ W_hh1,
    const float* __restrict__ b_ih1, const float* __restrict__ b_hh1,
    const float* __restrict__ W_ho)
{
    extern __shared__ float smem[];
    float* w0  = smem;                 // [k=256][u=4][gate=4][dup=2] =  8192 f
    float* w1  = smem + 8192;          // [k=512][u][gate][dup]       = 16384 f
    float* shA = smem + 24576;         // staging buf A: CH*128       =  8192 f
    float* shB = smem + 32768;         // staging buf B               =  8192 f
    float* red = smem + 40960;         // [u=4][bp=64][2]             =   512 f

    const int tid   = threadIdx.x;
    const int us    = blockIdx.x >> 1;
    const int bh    = blockIdx.x & 1;
    const int u     = tid >> 6;
    const int bp    = tid & 63;
    const int bbase = bh * 128 + bp * 2;
    const int lb    = bp * 2;          // local batch offset within staged chunk
    const int gu    = us * 4 + u;

    // stage duplicated weight slices (once)
    for (int idx = tid; idx < 256 * 16; idx += NT) {
        int k = idx >> 4, rem = idx & 15, uu = rem >> 2, gate = rem & 3;
        float w = W_hh0[(gate * H_SZ + us * 4 + uu) * H_SZ + k];
        int o = k * 32 + uu * 8 + gate * 2;
        w0[o] = w; w0[o + 1] = w;
    }
    for (int idx = tid; idx < 512 * 16; idx += NT) {
        int k = idx >> 4, rem = idx & 15, uu = rem >> 2, gate = rem & 3;
        int row = gate * H_SZ + us * 4 + uu;
        float w = (k < 256) ? W_ih1[row * H_SZ + k]
                            : W_hh1[row * H_SZ + (k - 256)];
        int o = k * 32 + uu * 8 + gate * 2;
        w1[o] = w; w1[o + 1] = w;
    }

    float bias0[4], bias1[4];
#pragma unroll
    for (int gate = 0; gate < 4; ++gate) {
        int row = gate * H_SZ + gu;
        bias0[gate] = b_ih0[row] + b_hh0[row];
        bias1[gate] = b_ih1[row] + b_hh1[row];
    }
    const float who = W_ho[gu];

    float c0a = 0.f, c0b = 0.f, c1a = 0.f, c1b = 0.f;
    __syncthreads();

    const float* w0u  = w0 + u * 8;                // layer0 W_hh0
    const float* w1au = w1 + u * 8;                // layer1 W_ih1
    const float* w1bu = w1 + 256 * 32 + u * 8;     // layer1 W_hh1

    for (int k = 1; k <= T_STEPS + 1; ++k) {
        const float* __restrict__ h0prev = g_h0[(k - 1) & 1] + bh * 128;
        const float* __restrict__ h1prev = g_h1[k & 1]       + bh * 128;

        u64 acc0[4], acc1[4];
#pragma unroll
        for (int g = 0; g < 4; ++g) {
            acc0[g] = pack2(bias0[g], bias0[g]);
            acc1[g] = pack2(bias1[g], bias1[g]);
        }

        // ---- fused pass over h0prev: layer0 (W_hh0) + layer1 input (W_ih1)
        stage_chunk(shA, h0prev, tid);
        __syncthreads();
#pragma unroll
        for (int c = 0; c < 4; ++c) {
            const float* cur = (c & 1) ? shB : shA;
            float*       nxt = (c & 1) ? shA : shB;
            if (c < 3) stage_chunk(nxt, h0prev + (c + 1) * CH * B_SZ, tid);
            else       stage_chunk(nxt, h1prev, tid);     // prefetch h1 chunk 0
            fused_chunk(acc0, acc1, cur,
                        w0u + c * CH * 32, w1au + c * CH * 32, lb);
            __syncthreads();
        }

        // ---- layer 0 epilogue: h0_k ----
        if (k <= T_STEPS) {
            float zi0, zi1, zf0, zf1, zg0, zg1, zo0, zo1;
            unpack2(acc0[0], zi0, zi1); unpack2(acc0[1], zf0, zf1);
            unpack2(acc0[2], zg0, zg1); unpack2(acc0[3], zo0, zo1);
            float cn0 = sigf(zf0) * c0a + sigf(zi0) * tanhf_(zg0);
            float cn1 = sigf(zf1) * c0b + sigf(zi1) * tanhf_(zg1);
            c0a = cn0; c0b = cn1;
            float2 ho;
            ho.x = sigf(zo0) * tanhf_(cn0);
            ho.y = sigf(zo1) * tanhf_(cn1);
            *reinterpret_cast<float2*>(g_h0[k & 1] + gu * B_SZ + bbase) = ho;
        }

        // ---- layer 1 recurrent pass (W_hh1 over h1prev) + epilogue: h1_{k-1}
        if (k >= 2) {
            // h1 chunk 0 is already staged in shA (from the c==3 prefetch)
#pragma unroll
            for (int c = 0; c < 4; ++c) {
                const float* cur = (c & 1) ? shB : shA;
                float*       nxt = (c & 1) ? shA : shB;
                if (c < 3) stage_chunk(nxt, h1prev + (c + 1) * CH * B_SZ, tid);
                single_chunk(acc1, cur, w1bu + c * CH * 32, lb);
                __syncthreads();
            }

            float zi0, zi1, zf0, zf1, zg0, zg1, zo0, zo1;
            unpack2(acc1[0], zi0, zi1); unpack2(acc1[1], zf0, zf1);
            unpack2(acc1[2], zg0, zg1); unpack2(acc1[3], zo0, zo1);
            float cn0 = sigf(zf0) * c1a + sigf(zi0) * tanhf_(zg0);
            float cn1 = sigf(zf1) * c1b + sigf(zi1) * tanhf_(zg1);
            c1a = cn0; c1b = cn1;
            float2 ho;
            ho.x = sigf(zo0) * tanhf_(cn0);
            ho.y = sigf(zo1) * tanhf_(cn1);
            *reinterpret_cast<float2*>(g_h1[(k - 1) & 1] + gu * B_SZ + bbase) = ho;

            // output partial: reduce this CTA's 4 units
            red[(u * 64 + bp) * 2]     = who * ho.x;
            red[(u * 64 + bp) * 2 + 1] = who * ho.y;
            __syncthreads();
            if (u == 0) {
                float s0 = red[bp * 2]             + red[(64 + bp) * 2] +
                           red[(128 + bp) * 2]     + red[(192 + bp) * 2];
                float s1 = red[bp * 2 + 1]         + red[(64 + bp) * 2 + 1] +
                           red[(128 + bp) * 2 + 1] + red[(192 + bp) * 2 + 1];
                int t0 = k - 2;
                g_part[(us * B_SZ + bbase)     * T_STEPS + t0] = s0;
                g_part[(us * B_SZ + bbase + 1) * T_STEPS + t0] = s1;
            }
            __syncthreads();   // red reused next phase
        }
        grid_sync();
    }
}

// ---------------- final: out[b][t] = b_ho + sum_us g_part[us][b][t] ----------
__global__ void reduce_kernel(const float* __restrict__ b_ho,
                              float* __restrict__ out) {
    int idx = blockIdx.x * blockDim.x + threadIdx.x;  // = b*512 + t
    float s = b_ho[0];
    const float* p = g_part + idx;
#pragma unroll 8
    for (int usx = 0; usx < 64; ++usx) s += p[usx * (B_SZ * T_STEPS)];
    out[idx] = s;
}

extern "C" void kernel_launch(void* const* d_in, const int* in_sizes, int n_in,
                              void* d_out, int out_size) {
    const float* latent = (const float*)d_in[0];
    const float* W_lh   = (const float*)d_in[1];
    const float* b_lh   = (const float*)d_in[2];
    // d_in[3] = W_ih0 (layer-0 inputs are all zero -> unused)
    const float* W_hh0  = (const float*)d_in[4];
    const float* b_ih0  = (const float*)d_in[5];
    const float* b_hh0  = (const float*)d_in[6];
    const float* W_ih1  = (const float*)d_in[7];
    const float* W_hh1  = (const float*)d_in[8];
    const float* b_ih1  = (const float*)d_in[9];
    const float* b_hh1  = (const float*)d_in[10];
    const float* W_ho   = (const float*)d_in[11];
    const float* b_ho   = (const float*)d_in[12];
    float* out = (float*)d_out;

    const int smem_bytes = (8192 + 16384 + 8192 + 8192 + 512) * sizeof(float); // 166912
    cudaFuncSetAttribute(lstm_kernel,
                         cudaFuncAttributeMaxDynamicSharedMemorySize, smem_bytes);

    init_kernel<<<B_SZ, H_SZ>>>(latent, W_lh, b_lh);
    lstm_kernel<<<NCTA, NT, smem_bytes>>>(W_hh0, b_ih0, b_hh0,
                                          W_ih1, W_hh1, b_ih1, b_hh1, W_ho);
    reduce_kernel<<<(B_SZ * T_STEPS) / 256, 256>>>(b_ho, out);
    (void)in_sizes; (void)n_in; (void)out_size;
}

// round 12
// speedup vs baseline: 1.2243x; 1.1515x over previous
#include <cuda_runtime.h>

#define T_STEPS 512
#define B_SZ    256
#define H_SZ    256
#define LDIM    128
#define NCTA    128   // 64 unit-slices x 2 batch-halves
#define NGRP    64    // CTAs per batch-half barrier group
#define NT      256   // threads: 4 units x 64 batch-pairs
#define WCH     128   // rows per staged wave

typedef unsigned long long u64;

// static device scratch (no allocations allowed)
__device__ __align__(16) float g_h0[2][H_SZ * B_SZ];   // [parity][unit][batch]
__device__ __align__(16) float g_h1[2][H_SZ * B_SZ];
__device__ float g_part[64 * B_SZ * T_STEPS];          // [us][b][t]
__device__ u64   g_ctr2[2 * 16];                       // one counter per bh, 128B apart

// ---------------- helpers ----------------
__device__ __forceinline__ void fma2(u64 &d, u64 a, u64 b) {
    asm("fma.rn.f32x2 %0, %1, %2, %0;" : "+l"(d) : "l"(a), "l"(b));
}
__device__ __forceinline__ u64 pack2(float lo, float hi) {
    u64 r; asm("mov.b64 %0, {%1, %2};" : "=l"(r) : "f"(lo), "f"(hi)); return r;
}
__device__ __forceinline__ void unpack2(u64 v, float &lo, float &hi) {
    asm("mov.b64 {%0, %1}, %2;" : "=f"(lo), "=f"(hi) : "l"(v));
}
__device__ __forceinline__ float ex2f(float x) {
    float r; asm("ex2.approx.f32 %0, %1;" : "=f"(r) : "f"(x)); return r;
}
__device__ __forceinline__ float rcpf(float x) {
    float r; asm("rcp.approx.f32 %0, %1;" : "=f"(r) : "f"(x)); return r;
}
__device__ __forceinline__ float sigf(float x) {
    return rcpf(1.0f + ex2f(-1.4426950408889634f * x));
}
__device__ __forceinline__ float tanhf_(float x) {
    float e = ex2f(2.8853900817779268f * x);   // e^{2x}
    return 1.0f - 2.0f * rcpf(e + 1.0f);
}
__device__ __forceinline__ unsigned smem_u32(const void* p) {
    unsigned a;
    asm("{ .reg .u64 t; cvta.to.shared.u64 t, %1; cvt.u32.u64 %0, t; }"
        : "=r"(a) : "l"(p));
    return a;
}

// per-batch-half re-entrant barrier (64 CTAs), graph-replay safe
__device__ __forceinline__ void group_sync(int bh) {
    __syncthreads();
    if (threadIdx.x == 0) {
        u64* ctr = &g_ctr2[bh * 16];
        u64 old;
        asm volatile("atom.release.gpu.add.u64 %0, [%1], %2;"
                     : "=l"(old) : "l"(ctr), "l"(1ULL) : "memory");
        u64 target = (old / NGRP + 1ULL) * (u64)NGRP;
        u64 v;
        do {
            asm volatile("ld.acquire.gpu.u64 %0, [%1];"
                         : "=l"(v) : "l"(ctr) : "memory");
        } while (v < target);
    }
    __syncthreads();
}

// stage WCH rows x 128 batch-floats via cp.async (L2-coherent, no reg round-trip)
__device__ __forceinline__ void stage_wave(unsigned sdst,
                                           const float* __restrict__ gsrc,
                                           int tid) {
#pragma unroll
    for (int j = 0; j < 16; ++j) {
        int idx = tid + j * NT;                 // 0..4095 float4 slots
        int row = idx >> 5;                     // 32 float4 per row
        int c4  = idx & 31;
        const float* src = gsrc + row * B_SZ + c4 * 4;
        unsigned dst = sdst + ((unsigned)idx << 4);
        asm volatile("cp.async.cg.shared.global [%0], [%1], 16;\n"
                     :: "r"(dst), "l"(src));
    }
    asm volatile("cp.async.commit_group;\n" ::: "memory");
}
__device__ __forceinline__ void stage_wait() {
    asm volatile("cp.async.wait_group 0;\n" ::: "memory");
}

// fused: accumulate acc0 (W_hh0) and acc1 (W_ih1) over one staged h0 wave
__device__ __forceinline__ void fused_span(u64 acc0[4], u64 acc1[4],
                                           const float* __restrict__ sh,
                                           const float* __restrict__ w0k,
                                           const float* __restrict__ w1k,
                                           int lb) {
#pragma unroll 8
    for (int kk = 0; kk < WCH; ++kk) {
        u64 hv = *reinterpret_cast<const u64*>(sh + kk * 128 + lb);
        const ulonglong2* p0 = reinterpret_cast<const ulonglong2*>(w0k + kk * 32);
        const ulonglong2* p1 = reinterpret_cast<const ulonglong2*>(w1k + kk * 32);
        ulonglong2 a0 = p0[0], b0 = p0[1];
        ulonglong2 a1 = p1[0], b1 = p1[1];
        fma2(acc0[0], hv, a0.x); fma2(acc0[1], hv, a0.y);
        fma2(acc0[2], hv, b0.x); fma2(acc0[3], hv, b0.y);
        fma2(acc1[0], hv, a1.x); fma2(acc1[1], hv, a1.y);
        fma2(acc1[2], hv, b1.x); fma2(acc1[3], hv, b1.y);
    }
}

// single: accumulate acc over one staged h1 wave (W_hh1)
__device__ __forceinline__ void single_span(u64 acc[4],
                                            const float* __restrict__ sh,
                                            const float* __restrict__ wk,
                                            int lb) {
#pragma unroll 8
    for (int kk = 0; kk < WCH; ++kk) {
        u64 hv = *reinterpret_cast<const u64*>(sh + kk * 128 + lb);
        const ulonglong2* p = reinterpret_cast<const ulonglong2*>(wk + kk * 32);
        ulonglong2 a = p[0], b = p[1];
        fma2(acc[0], hv, a.x); fma2(acc[1], hv, a.y);
        fma2(acc[2], hv, b.x); fma2(acc[3], hv, b.y);
    }
}

// ---------------- single persistent kernel: init + rollout + output ----------
// CTA r: us = r>>1 owns units [us*4, us*4+4), bh = r&1 owns batches [bh*128,+128)
// thread: u = tid>>6 (0..3), bp = tid&63 -> batches bbase=bh*128+bp*2 (+0,+1)
__global__ void __launch_bounds__(NT, 1) lstm_all(
    const float* __restrict__ latent,
    const float* __restrict__ W_lh,  const float* __restrict__ b_lh,
    const float* __restrict__ W_hh0,
    const float* __restrict__ b_ih0, const float* __restrict__ b_hh0,
    const float* __restrict__ W_ih1, const float* __restrict__ W_hh1,
    const float* __restrict__ b_ih1, const float* __restrict__ b_hh1,
    const float* __restrict__ W_ho,  const float* __restrict__ b_ho,
    float* __restrict__ out)
{
    extern __shared__ float smem[];
    float* w0  = smem;                 // [k=256][u=4][gate=4][dup=2] =  8192 f
    float* w1  = smem + 8192;          // [k=512][u][gate][dup]       = 16384 f
    float* sA  = smem + 24576;         // wave buf A: 128x128         = 16384 f
    float* sB  = smem + 40960;         // wave buf B                  = 16384 f
    float* red = smem + 57344;         // [u=4][bp=64][2]             =   512 f
    const unsigned sAa = smem_u32(sA);
    const unsigned sBa = smem_u32(sB);

    const int tid   = threadIdx.x;
    const int us    = blockIdx.x >> 1;
    const int bh    = blockIdx.x & 1;
    const int u     = tid >> 6;
    const int bp    = tid & 63;
    const int bbase = bh * 128 + bp * 2;
    const int lb    = bp * 2;
    const int gu    = us * 4 + u;

    // ---- stage duplicated weight slices (once) ----
    for (int idx = tid; idx < 256 * 16; idx += NT) {
        int k = idx >> 4, rem = idx & 15, uu = rem >> 2, gate = rem & 3;
        float w = W_hh0[(gate * H_SZ + us * 4 + uu) * H_SZ + k];
        int o = k * 32 + uu * 8 + gate * 2;
        w0[o] = w; w0[o + 1] = w;
    }
    for (int idx = tid; idx < 512 * 16; idx += NT) {
        int k = idx >> 4, rem = idx & 15, uu = rem >> 2, gate = rem & 3;
        int row = gate * H_SZ + us * 4 + uu;
        float w = (k < 256) ? W_ih1[row * H_SZ + k]
                            : W_hh1[row * H_SZ + (k - 256)];
        int o = k * 32 + uu * 8 + gate * 2;
        w1[o] = w; w1[o + 1] = w;
    }

    float bias0[4], bias1[4];
#pragma unroll
    for (int gate = 0; gate < 4; ++gate) {
        int row = gate * H_SZ + gu;
        bias0[gate] = b_ih0[row] + b_hh0[row];
        bias1[gate] = b_ih1[row] + b_hh1[row];
    }
    const float who = W_ho[gu];

    // ---- init phase: h_init = latent @ W_lh^T + b_lh for (gu, bbase/bbase+1)
    {
        const float* wl  = W_lh + gu * LDIM;
        const float* la  = latent + bbase * LDIM;
        const float* lb2 = latent + (bbase + 1) * LDIM;
        float aA = 0.f, aB = 0.f;
#pragma unroll 4
        for (int l = 0; l < LDIM; ++l) {
            float w = wl[l];
            aA = fmaf(w, la[l],  aA);
            aB = fmaf(w, lb2[l], aB);
        }
        float bl = b_lh[gu];
        float hA = aA + bl, hB = aB + bl;
        g_h0[0][gu * B_SZ + bbase]     = hA;
        g_h0[0][gu * B_SZ + bbase + 1] = hB;
        g_h1[0][gu * B_SZ + bbase]     = hA;
        g_h1[0][gu * B_SZ + bbase + 1] = hB;
    }
    group_sync(bh);   // also covers weight-smem visibility

    float c0a = 0.f, c0b = 0.f, c1a = 0.f, c1b = 0.f;

    const float* w0u  = w0 + u * 8;                // layer0 W_hh0
    const float* w1au = w1 + u * 8;                // layer1 W_ih1
    const float* w1bu = w1 + 256 * 32 + u * 8;     // layer1 W_hh1

    for (int k = 1; k <= T_STEPS + 1; ++k) {
        const float* __restrict__ h0p = g_h0[(k - 1) & 1] + bh * 128;
        const float* __restrict__ h1p = g_h1[k & 1]       + bh * 128;

        u64 acc0[4], acc1[4];
#pragma unroll
        for (int g = 0; g < 4; ++g) {
            acc0[g] = pack2(bias0[g], bias0[g]);
            acc1[g] = pack2(bias1[g], bias1[g]);
        }

        // S0: stage h0 wave0
        stage_wave(sAa, h0p, tid);
        stage_wait(); __syncthreads();

        // S1: stage h0 wave1, consume wave0 (fused layer0 + layer1-input)
        stage_wave(sBa, h0p + WCH * B_SZ, tid);
        fused_span(acc0, acc1, sA, w0u, w1au, lb);
        stage_wait(); __syncthreads();

        // S2: stage h1 wave0, consume h0 wave1; finish layer0
        stage_wave(sAa, h1p, tid);
        fused_span(acc0, acc1, sB, w0u + WCH * 32, w1au + WCH * 32, lb);
        if (k <= T_STEPS) {
            float zi0, zi1, zf0, zf1, zg0, zg1, zo0, zo1;
            unpack2(acc0[0], zi0, zi1); unpack2(acc0[1], zf0, zf1);
            unpack2(acc0[2], zg0, zg1); unpack2(acc0[3], zo0, zo1);
            float cn0 = sigf(zf0) * c0a + sigf(zi0) * tanhf_(zg0);
            float cn1 = sigf(zf1) * c0b + sigf(zi1) * tanhf_(zg1);
            c0a = cn0; c0b = cn1;
            float2 ho;
            ho.x = sigf(zo0) * tanhf_(cn0);
            ho.y = sigf(zo1) * tanhf_(cn1);
            *reinterpret_cast<float2*>(g_h0[k & 1] + gu * B_SZ + bbase) = ho;
        }
        stage_wait(); __syncthreads();

        // S3: stage h1 wave1, consume h1 wave0 (layer1 recurrent)
        stage_wave(sBa, h1p + WCH * B_SZ, tid);
        single_span(acc1, sA, w1bu, lb);
        stage_wait(); __syncthreads();

        // S4: consume h1 wave1; finish layer1 + output partial
        single_span(acc1, sB, w1bu + WCH * 32, lb);
        if (k >= 2) {
            float zi0, zi1, zf0, zf1, zg0, zg1, zo0, zo1;
            unpack2(acc1[0], zi0, zi1); unpack2(acc1[1], zf0, zf1);
            unpack2(acc1[2], zg0, zg1); unpack2(acc1[3], zo0, zo1);
            float cn0 = sigf(zf0) * c1a + sigf(zi0) * tanhf_(zg0);
            float cn1 = sigf(zf1) * c1b + sigf(zi1) * tanhf_(zg1);
            c1a = cn0; c1b = cn1;
            float2 ho;
            ho.x = sigf(zo0) * tanhf_(cn0);
            ho.y = sigf(zo1) * tanhf_(cn1);
            *reinterpret_cast<float2*>(g_h1[(k - 1) & 1] + gu * B_SZ + bbase) = ho;

            red[(u * 64 + bp) * 2]     = who * ho.x;
            red[(u * 64 + bp) * 2 + 1] = who * ho.y;
            __syncthreads();
            if (u == 0) {
                float s0 = red[bp * 2]             + red[(64 + bp) * 2] +
                           red[(128 + bp) * 2]     + red[(192 + bp) * 2];
                float s1 = red[bp * 2 + 1]         + red[(64 + bp) * 2 + 1] +
                           red[(128 + bp) * 2 + 1] + red[(192 + bp) * 2 + 1];
                int t0 = k - 2;
                g_part[(us * B_SZ + bbase)     * T_STEPS + t0] = s0;
                g_part[(us * B_SZ + bbase + 1) * T_STEPS + t0] = s1;
            }
        }
        group_sync(bh);
    }

    // ---- final output reduce: out[b][t] = b_ho + sum_us g_part[us][b][t]
    // this bh group's g_part is complete & visible after the last group_sync
    const float bo = b_ho[0];
    int base = (us * NT + tid) * 4;                 // 0..65535 within group
#pragma unroll
    for (int j = 0; j < 4; ++j) {
        int e    = base + j;
        int brel = e >> 9;
        int t    = e & 511;
        int b    = bh * 128 + brel;
        float s = bo;
        const float* p = g_part + b * T_STEPS + t;
#pragma unroll 8
        for (int usx = 0; usx < 64; ++usx) s += p[usx * (B_SZ * T_STEPS)];
        out[b * T_STEPS + t] = s;
    }
}

extern "C" void kernel_launch(void* const* d_in, const int* in_sizes, int n_in,
                              void* d_out, int out_size) {
    const float* latent = (const float*)d_in[0];
    const float* W_lh   = (const float*)d_in[1];
    const float* b_lh   = (const float*)d_in[2];
    // d_in[3] = W_ih0 (layer-0 inputs are all zero -> unused)
    const float* W_hh0  = (const float*)d_in[4];
    const float* b_ih0  = (const float*)d_in[5];
    const float* b_hh0  = (const float*)d_in[6];
    const float* W_ih1  = (const float*)d_in[7];
    const float* W_hh1  = (const float*)d_in[8];
    const float* b_ih1  = (const float*)d_in[9];
    const float* b_hh1  = (const float*)d_in[10];
    const float* W_ho   = (const float*)d_in[11];
    const float* b_ho   = (const float*)d_in[12];
    float* out = (float*)d_out;

    const int smem_bytes = 57856 * sizeof(float);   // 231,424 B (< 227 KB cap)
    cudaFuncSetAttribute(lstm_all,
                         cudaFuncAttributeMaxDynamicSharedMemorySize, smem_bytes);

    lstm_all<<<NCTA, NT, smem_bytes>>>(latent, W_lh, b_lh,
                                       W_hh0, b_ih0, b_hh0,
                                       W_ih1, W_hh1, b_ih1, b_hh1,
                                       W_ho, b_ho, out);
    (void)in_sizes; (void)n_in; (void)out_size;
}